// round 1
// baseline (speedup 1.0000x reference)
#include <cuda_runtime.h>
#include <cstdint>

// Problem constants (fixed by the reference).
constexpr int    N_USERS = 100000;
constexpr int    N_ITEMS = 100000;
constexpr int    DIM     = 128;
constexpr size_t SEG     = (size_t)N_USERS * DIM;   // 12.8M floats per scratch slot

// Scratch: 4 slots (LI_u, L_u, LI_i, L_i), each [100000,128] fp32.
// Static __device__ array => no allocation inside kernel_launch (harness rule).
__device__ float g_scratch[4ull * 100000ull * 128ull];

// ---------------------------------------------------------------------------
// Kernel 1: zero all scratch (float4 stores, grid-stride)
// ---------------------------------------------------------------------------
__global__ void zero_scratch(size_t n4) {
    float4* p = reinterpret_cast<float4*>(g_scratch);
    size_t i = (size_t)blockIdx.x * blockDim.x + threadIdx.x;
    size_t stride = (size_t)gridDim.x * blockDim.x;
    float4 z = make_float4(0.f, 0.f, 0.f, 0.f);
    for (; i < n4; i += stride) p[i] = z;
}

// ---------------------------------------------------------------------------
// Kernel 2: all four SpMMs in one launch (blockIdx.y selects the matrix).
// One warp handles 32 nnz: coalesced index loads, then per-nnz the full warp
// gathers one 512B ebs row and scatter-adds with red.global.add.v4.f32.
// ---------------------------------------------------------------------------
__device__ __forceinline__ void red_add_v4(float* dst, float x, float y, float z, float w) {
    asm volatile("red.global.add.v4.f32 [%0], {%1, %2, %3, %4};"
                 :: "l"(dst), "f"(x), "f"(y), "f"(z), "f"(w)
                 : "memory");
}

__global__ void __launch_bounds__(256) spmm4(
    const float* __restrict__ ebs,
    const int* __restrict__ r0, const int* __restrict__ c0, const float* __restrict__ v0,
    const int* __restrict__ r1, const int* __restrict__ c1, const float* __restrict__ v1,
    const int* __restrict__ r2, const int* __restrict__ c2, const float* __restrict__ v2,
    const int* __restrict__ r3, const int* __restrict__ c3, const float* __restrict__ v3,
    int nnz)
{
    const int slot = blockIdx.y;
    const int* rows; const int* cols; const float* vals;
    switch (slot) {
        case 0:  rows = r0; cols = c0; vals = v0; break;
        case 1:  rows = r1; cols = c1; vals = v1; break;
        case 2:  rows = r2; cols = c2; vals = v2; break;
        default: rows = r3; cols = c3; vals = v3; break;
    }
    float* out = g_scratch + (size_t)slot * SEG;

    const int lane    = threadIdx.x & 31;
    const int warp_id = (blockIdx.x * blockDim.x + threadIdx.x) >> 5;
    const int base    = warp_id * 32;
    if (base >= nnz) return;
    const int cnt = min(32, nnz - base);

    int   r = 0, c = 0; float v = 0.f;
    if (lane < cnt) {
        r = rows[base + lane];
        c = cols[base + lane];
        v = vals[base + lane];
    }

    #pragma unroll 4
    for (int j = 0; j < cnt; j++) {
        const int   rj = __shfl_sync(0xffffffffu, r, j);
        const int   cj = __shfl_sync(0xffffffffu, c, j);
        const float vj = __shfl_sync(0xffffffffu, v, j);
        const float4 e = *reinterpret_cast<const float4*>(ebs + (size_t)cj * DIM + lane * 4);
        float* dst = out + (size_t)rj * DIM + lane * 4;
        red_add_v4(dst, e.x * vj, e.y * vj, e.z * vj, e.w * vj);
    }
}

// ---------------------------------------------------------------------------
// Kernel 3: fused fold GEMM + gate + leaky relu.
//   out = LI @ Wside + (L * ent) @ Wdot ; leaky_relu(0.2)
// Block: 256 threads, 32 rows x 128 cols tile. Thread (tx,ty) -> 4x4 microtile.
// A tiles (LI and L*ent) live in shared; W rows stream through L1/L2
// (W is only 64KB each and reused by every block -> cache-resident).
// ---------------------------------------------------------------------------
constexpr int TR = 32;  // rows per block

__global__ void __launch_bounds__(256) fold_gemm(
    const float* __restrict__ ebs,
    const float* __restrict__ Wsu, const float* __restrict__ Wdu,
    const float* __restrict__ Wsi, const float* __restrict__ Wdi,
    float* __restrict__ outp)
{
    const int fold = blockIdx.y;
    const float* LI  = g_scratch + (size_t)(2 * fold)     * SEG;
    const float* L   = g_scratch + (size_t)(2 * fold + 1) * SEG;
    const float* ent = ebs  + (size_t)fold * SEG;   // user: rows [0,100k), item: [100k,200k)
    const float* Ws  = fold ? Wsi : Wsu;
    const float* Wd  = fold ? Wdi : Wdu;
    float* out       = outp + (size_t)fold * SEG;

    __shared__ float As[TR][DIM];   // LI rows
    __shared__ float Bs[TR][DIM];   // (L * ent) rows

    const int row0 = blockIdx.x * TR;
    const int tid  = threadIdx.x;

    // Cooperative load: 32 rows x 128 cols, fully coalesced float4.
    for (int i = tid; i < TR * (DIM / 4); i += 256) {
        const int rr = i >> 5;           // 32 float4 per row
        const int c4 = i & 31;
        const size_t g = (size_t)(row0 + rr) * DIM + c4 * 4;
        const float4 li = *reinterpret_cast<const float4*>(LI  + g);
        const float4 ll = *reinterpret_cast<const float4*>(L   + g);
        const float4 ee = *reinterpret_cast<const float4*>(ent + g);
        *reinterpret_cast<float4*>(&As[rr][c4 * 4]) = li;
        float4 b = make_float4(ll.x * ee.x, ll.y * ee.y, ll.z * ee.z, ll.w * ee.w);
        *reinterpret_cast<float4*>(&Bs[rr][c4 * 4]) = b;
    }
    __syncthreads();

    const int tx = tid & 31;   // cols 4*tx .. 4*tx+3
    const int ty = tid >> 5;   // rows 4*ty .. 4*ty+3

    float acc[4][4] = {};

    #pragma unroll 4
    for (int k = 0; k < DIM; k++) {
        const float4 ws = *reinterpret_cast<const float4*>(Ws + (size_t)k * DIM + tx * 4);
        const float4 wd = *reinterpret_cast<const float4*>(Wd + (size_t)k * DIM + tx * 4);
        #pragma unroll
        for (int r = 0; r < 4; r++) {
            const float a = As[ty * 4 + r][k];   // broadcast within warp
            const float b = Bs[ty * 4 + r][k];
            acc[r][0] += a * ws.x + b * wd.x;
            acc[r][1] += a * ws.y + b * wd.y;
            acc[r][2] += a * ws.z + b * wd.z;
            acc[r][3] += a * ws.w + b * wd.w;
        }
    }

    #pragma unroll
    for (int r = 0; r < 4; r++) {
        float4 o;
        float x;
        x = acc[r][0]; o.x = (x > 0.f) ? x : 0.2f * x;
        x = acc[r][1]; o.y = (x > 0.f) ? x : 0.2f * x;
        x = acc[r][2]; o.z = (x > 0.f) ? x : 0.2f * x;
        x = acc[r][3]; o.w = (x > 0.f) ? x : 0.2f * x;
        *reinterpret_cast<float4*>(out + (size_t)(row0 + ty * 4 + r) * DIM + tx * 4) = o;
    }
}

// ---------------------------------------------------------------------------
// Launch contract
// ---------------------------------------------------------------------------
extern "C" void kernel_launch(void* const* d_in, const int* in_sizes, int n_in,
                              void* d_out, int out_size)
{
    const float* ebs  = (const float*)d_in[0];
    const float* Wsu  = (const float*)d_in[1];
    const float* Wdu  = (const float*)d_in[2];
    const float* Wsi  = (const float*)d_in[3];
    const float* Wdi  = (const float*)d_in[4];
    const float* vLIu = (const float*)d_in[5];
    const float* vLu  = (const float*)d_in[6];
    const float* vLIi = (const float*)d_in[7];
    const float* vLi  = (const float*)d_in[8];
    const int* rLIu = (const int*)d_in[9];
    const int* cLIu = (const int*)d_in[10];
    const int* rLu  = (const int*)d_in[11];
    const int* cLu  = (const int*)d_in[12];
    const int* rLIi = (const int*)d_in[13];
    const int* cLIi = (const int*)d_in[14];
    const int* rLi  = (const int*)d_in[15];
    const int* cLi  = (const int*)d_in[16];
    float* out = (float*)d_out;

    const int nnz = in_sizes[5];   // 1,000,000

    // 1) zero scratch (4 * 12.8M floats = 12.8M float4)
    {
        const size_t n4 = 4 * SEG / 4;
        zero_scratch<<<6250, 256>>>(n4);
    }

    // 2) four SpMMs in one launch
    {
        const int warps  = (nnz + 31) / 32;
        const int blocks = (warps + 7) / 8;   // 8 warps / 256-thread block
        dim3 grid(blocks, 4);
        spmm4<<<grid, 256>>>(ebs,
                             rLIu, cLIu, vLIu,
                             rLu,  cLu,  vLu,
                             rLIi, cLIi, vLIi,
                             rLi,  cLi,  vLi,
                             nnz);
    }

    // 3) fused fold GEMM + gate + leaky relu, both folds in one launch
    {
        dim3 grid(N_USERS / TR, 2);
        fold_gemm<<<grid, 256>>>(ebs, Wsu, Wdu, Wsi, Wdi, out);
    }
}